// round 11
// baseline (speedup 1.0000x reference)
#include <cuda_runtime.h>
#include <cstdint>

#define NB 4
#define NS 512
#define ND 768
#define NL 64

#define BM 64
#define BN 64
#define BK 32
#define LT 4
#define NCH (ND / BK)   // 24

// SMEM floats: As[2][64][40], Bs[2][64][40], Us[4][768]
#define ST_STRIDE 40
#define ST_FLOATS (BM * ST_STRIDE)        // 2560 per stage per matrix
#define OFF_B (2 * ST_FLOATS)             // 5120
#define OFF_U (4 * ST_FLOATS)             // 10240
#define SMEM_BYTES ((4 * ST_FLOATS + LT * ND) * 4)   // 53248

// Scratch for the rank-1 epilogue terms.
__device__ float g_rowadd[NB * NL * NS];  // head . Wh + bias
__device__ float g_coladd[NB * NL * NS];  // dep  . Wd

__device__ __forceinline__ uint32_t f2tf(float x) {
    uint32_t r;
    asm("cvt.rna.tf32.f32 %0, %1;" : "=r"(r) : "f"(x));
    return r;
}

__device__ __forceinline__ void mma_tf32(float* c, const uint32_t* a,
                                         uint32_t b0, uint32_t b1) {
    asm volatile(
        "mma.sync.aligned.m16n8k8.row.col.f32.tf32.tf32.f32 "
        "{%0,%1,%2,%3}, {%4,%5,%6,%7}, {%8,%9}, {%0,%1,%2,%3};"
        : "+f"(c[0]), "+f"(c[1]), "+f"(c[2]), "+f"(c[3])
        : "r"(a[0]), "r"(a[1]), "r"(a[2]), "r"(a[3]), "r"(b0), "r"(b1));
}

// ---------------------------------------------------------------------------
// Stage 1 (unchanged, known-good): rank-1 epilogue terms.
// ---------------------------------------------------------------------------
__global__ void __launch_bounds__(256) stage1_kernel(
    const float* __restrict__ head, const float* __restrict__ dep,
    const float* __restrict__ W, const float* __restrict__ bias)
{
    __shared__ float Xs[32][36];
    __shared__ float Ws[64][33];

    const int which = blockIdx.y;
    const float* X = which ? dep : head;
    const int b  = blockIdx.x >> 4;
    const int i0 = (blockIdx.x & 15) * 32;

    const int t  = threadIdx.x;
    const int l  = t & 63;
    const int rg = t >> 6;
    const int fr = t >> 3;
    const int fc = (t & 7) * 4;

    float acc[8];
#pragma unroll
    for (int j = 0; j < 8; j++) acc[j] = 0.f;

    for (int k0 = 0; k0 < ND; k0 += 32) {
        __syncthreads();
        float4 xv = *(const float4*)&X[((size_t)(b * NS + i0 + fr)) * ND + k0 + fc];
        *(float4*)&Xs[fr][fc] = xv;
        float4 w0 = *(const float4*)&W[(size_t)fr * (2 * ND) + which * ND + k0 + fc];
        float4 w1 = *(const float4*)&W[(size_t)(fr + 32) * (2 * ND) + which * ND + k0 + fc];
        Ws[fr][fc + 0] = w0.x; Ws[fr][fc + 1] = w0.y;
        Ws[fr][fc + 2] = w0.z; Ws[fr][fc + 3] = w0.w;
        Ws[fr + 32][fc + 0] = w1.x; Ws[fr + 32][fc + 1] = w1.y;
        Ws[fr + 32][fc + 2] = w1.z; Ws[fr + 32][fc + 3] = w1.w;
        __syncthreads();
#pragma unroll
        for (int kk = 0; kk < 32; kk++) {
            float wv = Ws[l][kk];
#pragma unroll
            for (int j = 0; j < 8; j++)
                acc[j] += Xs[rg + 4 * j][kk] * wv;
        }
    }

    const float bb = which ? 0.f : bias[l];
    float* dst = which ? g_coladd : g_rowadd;
#pragma unroll
    for (int j = 0; j < 8; j++)
        dst[((size_t)(b * NL + l)) * NS + i0 + rg + 4 * j] = acc[j] + bb;
}

// ---------------------------------------------------------------------------
// Main kernel: tf32 mma.sync, 2-stage double buffer, pair-interleaved SMEM
// layout (newc = kg*8 + (tig^(row&3))*2 + h) so every fragment pair
// (kc, kc+4) is ONE conflict-free LDS.64. Fill is 16 conflict-free STS.32.
// grid = (8, 8, 64), block = 256 (8 warps, 2x4 warp grid, 32x16 warp tile).
// ---------------------------------------------------------------------------
__global__ void __launch_bounds__(256, 2) biaffine_main_kernel(
    const float* __restrict__ head, const float* __restrict__ dep,
    const float* __restrict__ U, float* __restrict__ out)
{
    extern __shared__ float smf[];
    float* AsBase = smf;            // [2][64][40]
    float* BsBase = smf + OFF_B;    // [2][64][40]
    float* Us     = smf + OFF_U;    // [4][768], pair-interleaved (no row xor)

    const int o0 = blockIdx.x * BN;
    const int i0 = blockIdx.y * BM;
    const int b  = blockIdx.z >> 4;
    const int l0 = (blockIdx.z & 15) * LT;

    const int t    = threadIdx.x;
    const int warp = t >> 5;
    const int lane = t & 31;
    const int wm   = warp >> 2;   // 0..1
    const int wn   = warp & 3;    // 0..3
    const int gid  = lane >> 2;   // 0..7
    const int tig  = lane & 3;    // 0..3

    float acc[LT][2][2][4];
#pragma unroll
    for (int l = 0; l < LT; l++)
#pragma unroll
        for (int mt = 0; mt < 2; mt++)
#pragma unroll
            for (int nt = 0; nt < 2; nt++)
#pragma unroll
                for (int q = 0; q < 4; q++) acc[l][mt][nt][q] = 0.f;

    // Preload 4 U rows into SMEM with pair-interleaved columns (no row xor):
    // orig (l, kk) -> Us[l*768 + (kk&~31) + (c>>3)*8 + (c&3)*2 + ((c>>2)&1)], c=kk&31.
#pragma unroll
    for (int j = 0; j < 12; j++) {
        const int p  = t + 256 * j;            // 0..3071
        const int l  = p >> 9 >> 0 ? (p / 768) : 0;  // avoided; compute directly below
        const int ll = p / 768;
        const int kk = p - ll * 768;
        const int c  = kk & 31;
        const int nc = ((c >> 3) << 3) + ((c & 3) << 1) + ((c >> 2) & 1);
        Us[ll * 768 + (kk & ~31) + nc] = __ldg(U + (size_t)l0 * ND + p);
        (void)l;
    }

    // Fill geometry: fr = row (0..31), q selects float4; value j has tig=j.
    const int fr  = t >> 3;
    const int q   = t & 7;
    const int q2  = q >> 1;
    const int q1  = q & 1;
    const int fr2 = fr & 3;
    const int jx0 = ((0 ^ fr2) << 1);
    const int jx1 = ((1 ^ fr2) << 1);
    const int jx2 = ((2 ^ fr2) << 1);
    const int jx3 = ((3 ^ fr2) << 1);
    const int fbase = q2 * 8 + q1;   // within-chunk column base for this thread

    const float* hp = &head[((size_t)(b * NS + i0 + fr)) * ND + q * 4];
    const float* dp = &dep [((size_t)(b * NS + o0 + fr)) * ND + q * 4];

#define SCATTER4(dst, row, v)                                             \
    do {                                                                  \
        float* _p = (dst) + (row) * ST_STRIDE + fbase;                    \
        _p[jx0] = __uint_as_float(f2tf((v).x));                           \
        _p[jx1] = __uint_as_float(f2tf((v).y));                           \
        _p[jx2] = __uint_as_float(f2tf((v).z));                           \
        _p[jx3] = __uint_as_float(f2tf((v).w));                           \
    } while (0)

    // Fill stage 0 with chunk 0.
    {
        float4 ha = *(const float4*)(hp);
        float4 hb = *(const float4*)(hp + 32 * ND);
        float4 da = *(const float4*)(dp);
        float4 db = *(const float4*)(dp + 32 * ND);
        SCATTER4(AsBase, fr, ha);
        SCATTER4(AsBase, fr + 32, hb);
        SCATTER4(BsBase, fr, da);
        SCATTER4(BsBase, fr + 32, db);
    }
    __syncthreads();

    // Hoisted fragment-read offsets (floats). XOR term is thread-constant.
    const int tigx = ((tig ^ (gid & 3)) << 1);
    const int arow = (wm * 32 + gid) * ST_STRIDE + tigx;   // + {0,8,16,24}*stride
    const int brow = (wn * 16 + gid) * ST_STRIDE + tigx;   // + {0,8}*stride
    const int uoff = tig * 2;

    for (int ch = 0; ch < NCH; ch++) {
        const int cur = ch & 1;
        const int k0 = ch * BK;
        const bool more = (ch < NCH - 1);

        // 1) LDG next chunk (latency hidden under the MMAs).
        float4 ha, hb, da, db;
        if (more) {
            ha = *(const float4*)(hp + k0 + BK);
            hb = *(const float4*)(hp + k0 + BK + 32 * ND);
            da = *(const float4*)(dp + k0 + BK);
            db = *(const float4*)(dp + k0 + BK + 32 * ND);
        }

        // 2) MMAs on current stage. All fragment loads are LDS.64.
        const float* Ac = AsBase + cur * ST_FLOATS;
        const float* Bc = BsBase + cur * ST_FLOATS;
        const float* ub = Us + k0 + uoff;
#pragma unroll
        for (int kt = 0; kt < 4; kt++) {
            const int kb = kt * 8;
            float2 A00 = *(const float2*)(Ac + arow + kb);
            float2 A01 = *(const float2*)(Ac + arow + 8 * ST_STRIDE + kb);
            float2 A10 = *(const float2*)(Ac + arow + 16 * ST_STRIDE + kb);
            float2 A11 = *(const float2*)(Ac + arow + 24 * ST_STRIDE + kb);
            uint32_t a[2][4];
            a[0][0] = __float_as_uint(A00.x); a[0][1] = __float_as_uint(A01.x);
            a[0][2] = __float_as_uint(A00.y); a[0][3] = __float_as_uint(A01.y);
            a[1][0] = __float_as_uint(A10.x); a[1][1] = __float_as_uint(A11.x);
            a[1][2] = __float_as_uint(A10.y); a[1][3] = __float_as_uint(A11.y);

            float2 B0 = *(const float2*)(Bc + brow + kb);
            float2 B1 = *(const float2*)(Bc + brow + 8 * ST_STRIDE + kb);

#pragma unroll
            for (int l = 0; l < LT; l++) {
                const float2 up = *(const float2*)(ub + l * ND + kb);
                {
                    const uint32_t b0 = __float_as_uint(B0.x * up.x);
                    const uint32_t b1 = __float_as_uint(B0.y * up.y);
                    mma_tf32(acc[l][0][0], a[0], b0, b1);
                    mma_tf32(acc[l][1][0], a[1], b0, b1);
                }
                {
                    const uint32_t b0 = __float_as_uint(B1.x * up.x);
                    const uint32_t b1 = __float_as_uint(B1.y * up.y);
                    mma_tf32(acc[l][0][1], a[0], b0, b1);
                    mma_tf32(acc[l][1][1], a[1], b0, b1);
                }
            }
        }

        // 3) cvt + conflict-free scatter STS into the other stage.
        if (more) {
            float* An = AsBase + (cur ^ 1) * ST_FLOATS;
            float* Bn = BsBase + (cur ^ 1) * ST_FLOATS;
            SCATTER4(An, fr, ha);
            SCATTER4(An, fr + 32, hb);
            SCATTER4(Bn, fr, da);
            SCATTER4(Bn, fr + 32, db);
            __syncthreads();   // one barrier per chunk
        }
    }

    // Epilogue: + rowadd[b,l,i] + coladd[b,l,o]  (bias folded into rowadd).
#pragma unroll
    for (int l = 0; l < LT; l++) {
        const int lg = l0 + l;
        const float* radd = &g_rowadd[((size_t)(b * NL + lg)) * NS + i0];
        const float* cadd = &g_coladd[((size_t)(b * NL + lg)) * NS + o0];
        float* op = out + (((size_t)(b * NL + lg)) * NS + i0) * NS + o0;
#pragma unroll
        for (int mt = 0; mt < 2; mt++) {
            const int r0 = wm * 32 + mt * 16 + gid;
            const float ra0 = radd[r0];
            const float ra1 = radd[r0 + 8];
#pragma unroll
            for (int nt = 0; nt < 2; nt++) {
                const int c = wn * 16 + nt * 8 + 2 * tig;
                const float2 ca = *(const float2*)&cadd[c];
                float2 v0, v1;
                v0.x = acc[l][mt][nt][0] + ra0 + ca.x;
                v0.y = acc[l][mt][nt][1] + ra0 + ca.y;
                v1.x = acc[l][mt][nt][2] + ra1 + ca.x;
                v1.y = acc[l][mt][nt][3] + ra1 + ca.y;
                *(float2*)&op[(size_t)r0 * NS + c]       = v0;
                *(float2*)&op[(size_t)(r0 + 8) * NS + c] = v1;
            }
        }
    }
}

extern "C" void kernel_launch(void* const* d_in, const int* in_sizes, int n_in,
                              void* d_out, int out_size) {
    const float* head = (const float*)d_in[0];
    const float* dep  = (const float*)d_in[1];
    const float* U    = (const float*)d_in[2];
    const float* W    = (const float*)d_in[3];
    const float* bias = (const float*)d_in[4];
    float* out = (float*)d_out;

    cudaFuncSetAttribute(biaffine_main_kernel,
                         cudaFuncAttributeMaxDynamicSharedMemorySize, SMEM_BYTES);

    stage1_kernel<<<dim3(NB * (NS / 32), 2), 256>>>(head, dep, W, bias);
    biaffine_main_kernel<<<dim3(NS / BN, NS / BM, NB * (NL / LT)), 256, SMEM_BYTES>>>(
        head, dep, U, out);
}

// round 13
// speedup vs baseline: 1.0727x; 1.0727x over previous
#include <cuda_runtime.h>
#include <cstdint>

#define NB 4
#define NS 512
#define ND 768
#define NL 64

#define BM 64          // i rows per CTA
#define BN 128         // o cols per CTA
#define BK 32
#define LT 2           // labels per CTA (pre-scaled A per label)
#define NCH (ND / BK)  // 24

// SMEM floats per stage: A0[64][36], A1[64][36], B[128][36] = 9216
#define TSTR 36
#define A_FLOATS (BM * TSTR)               // 2304
#define B_FLOATS (BN * TSTR)               // 4608
#define SF (2 * A_FLOATS + B_FLOATS)       // 9216 per stage
#define OFF_U (2 * SF)                     // 18432
#define SMEM_BYTES ((2 * SF + LT * ND) * 4)  // 79872

// Scratch for the rank-1 epilogue terms.
__device__ float g_rowadd[NB * NL * NS];  // head . Wh + bias
__device__ float g_coladd[NB * NL * NS];  // dep  . Wd

__device__ __forceinline__ uint32_t f2tf(float x) {
    uint32_t r;
    asm("cvt.rna.tf32.f32 %0, %1;" : "=r"(r) : "f"(x));
    return r;
}

__device__ __forceinline__ void mma_tf32(float* c, const uint32_t* a,
                                         uint32_t b0, uint32_t b1) {
    asm volatile(
        "mma.sync.aligned.m16n8k8.row.col.f32.tf32.tf32.f32 "
        "{%0,%1,%2,%3}, {%4,%5,%6,%7}, {%8,%9}, {%0,%1,%2,%3};"
        : "+f"(c[0]), "+f"(c[1]), "+f"(c[2]), "+f"(c[3])
        : "r"(a[0]), "r"(a[1]), "r"(a[2]), "r"(a[3]), "r"(b0), "r"(b1));
}

// ---------------------------------------------------------------------------
// Stage 1 (unchanged, known-good): rank-1 epilogue terms.
// ---------------------------------------------------------------------------
__global__ void __launch_bounds__(256) stage1_kernel(
    const float* __restrict__ head, const float* __restrict__ dep,
    const float* __restrict__ W, const float* __restrict__ bias)
{
    __shared__ float Xs[32][36];
    __shared__ float Ws[64][33];

    const int which = blockIdx.y;
    const float* X = which ? dep : head;
    const int b  = blockIdx.x >> 4;
    const int i0 = (blockIdx.x & 15) * 32;

    const int t  = threadIdx.x;
    const int l  = t & 63;
    const int rg = t >> 6;
    const int fr = t >> 3;
    const int fc = (t & 7) * 4;

    float acc[8];
#pragma unroll
    for (int j = 0; j < 8; j++) acc[j] = 0.f;

    for (int k0 = 0; k0 < ND; k0 += 32) {
        __syncthreads();
        float4 xv = *(const float4*)&X[((size_t)(b * NS + i0 + fr)) * ND + k0 + fc];
        *(float4*)&Xs[fr][fc] = xv;
        float4 w0 = *(const float4*)&W[(size_t)fr * (2 * ND) + which * ND + k0 + fc];
        float4 w1 = *(const float4*)&W[(size_t)(fr + 32) * (2 * ND) + which * ND + k0 + fc];
        Ws[fr][fc + 0] = w0.x; Ws[fr][fc + 1] = w0.y;
        Ws[fr][fc + 2] = w0.z; Ws[fr][fc + 3] = w0.w;
        Ws[fr + 32][fc + 0] = w1.x; Ws[fr + 32][fc + 1] = w1.y;
        Ws[fr + 32][fc + 2] = w1.z; Ws[fr + 32][fc + 3] = w1.w;
        __syncthreads();
#pragma unroll
        for (int kk = 0; kk < 32; kk++) {
            float wv = Ws[l][kk];
#pragma unroll
            for (int j = 0; j < 8; j++)
                acc[j] += Xs[rg + 4 * j][kk] * wv;
        }
    }

    const float bb = which ? 0.f : bias[l];
    float* dst = which ? g_coladd : g_rowadd;
#pragma unroll
    for (int j = 0; j < 8; j++)
        dst[((size_t)(b * NL + l)) * NS + i0 + rg + 4 * j] = acc[j] + bb;
}

// ---------------------------------------------------------------------------
// Main kernel: tf32 mma.sync. Per CTA: 64(i) x 128(o) tile for LT=2 labels.
// A tiles are PRE-SCALED per label during the fill (head * U[l], rna->tf32),
// B (dep) tile is shared. Inner loop is pure LDS + MMA: no FMUL, no U loads.
// 2-stage double buffer, one barrier per chunk.
// grid = (4, 8, 128), block = 256 (8 warps, 2x4 warp grid, 32x32 warp tile/label).
// ---------------------------------------------------------------------------
__global__ void __launch_bounds__(256, 2) biaffine_main_kernel(
    const float* __restrict__ head, const float* __restrict__ dep,
    const float* __restrict__ U, float* __restrict__ out)
{
    extern __shared__ float smf[];
    float* Us = smf + OFF_U;   // [2][768]

    const int o0 = blockIdx.x * BN;
    const int i0 = blockIdx.y * BM;
    const int b  = blockIdx.z >> 5;          // 32 label groups of 2
    const int l0 = (blockIdx.z & 31) * LT;

    const int t    = threadIdx.x;
    const int warp = t >> 5;
    const int lane = t & 31;
    const int wm   = warp >> 2;   // 0..1  (rows)
    const int wn   = warp & 3;    // 0..3  (cols)
    const int gid  = lane >> 2;   // 0..7
    const int tig  = lane & 3;    // 0..3

    float acc[LT][2][4][4];       // [label][mt][nt][quad]
#pragma unroll
    for (int l = 0; l < LT; l++)
#pragma unroll
        for (int mt = 0; mt < 2; mt++)
#pragma unroll
            for (int nt = 0; nt < 4; nt++)
#pragma unroll
                for (int q = 0; q < 4; q++) acc[l][mt][nt][q] = 0.f;

    // Preload the 2 U rows (1536 contiguous floats) into SMEM once.
    {
        const float4* usrc = (const float4*)(U + (size_t)l0 * ND);
        float4* udst = (float4*)Us;
        if (t < 128) {
            udst[t]       = __ldg(&usrc[t]);
            udst[t + 128] = __ldg(&usrc[t + 128]);
            udst[t + 256] = __ldg(&usrc[t + 256]);
        }
    }

    // Fill geometry: fr = 0..31, fc = float4 column.
    const int fr = t >> 3;
    const int fc = (t & 7) * 4;
    const float* hp = &head[((size_t)(b * NS + i0 + fr)) * ND + fc];
    const float* dp = &dep [((size_t)(b * NS + o0 + fr)) * ND + fc];
    __syncthreads();   // Us visible before first fill reads it

#define CVT4(v) do { \
        (v).x = __uint_as_float(f2tf((v).x)); (v).y = __uint_as_float(f2tf((v).y)); \
        (v).z = __uint_as_float(f2tf((v).z)); (v).w = __uint_as_float(f2tf((v).w)); \
    } while (0)

#define FILL_STAGE(stg, h0, h1, d0, d1, d2, d3, u0, u1)                        \
    do {                                                                       \
        float* A0 = smf + (stg) * SF;                                          \
        float* A1 = A0 + A_FLOATS;                                             \
        float* Bb = A1 + A_FLOATS;                                             \
        float4 v;                                                              \
        v.x = (h0).x * (u0).x; v.y = (h0).y * (u0).y;                          \
        v.z = (h0).z * (u0).z; v.w = (h0).w * (u0).w; CVT4(v);                 \
        *(float4*)&A0[fr * TSTR + fc] = v;                                     \
        v.x = (h1).x * (u0).x; v.y = (h1).y * (u0).y;                          \
        v.z = (h1).z * (u0).z; v.w = (h1).w * (u0).w; CVT4(v);                 \
        *(float4*)&A0[(fr + 32) * TSTR + fc] = v;                              \
        v.x = (h0).x * (u1).x; v.y = (h0).y * (u1).y;                          \
        v.z = (h0).z * (u1).z; v.w = (h0).w * (u1).w; CVT4(v);                 \
        *(float4*)&A1[fr * TSTR + fc] = v;                                     \
        v.x = (h1).x * (u1).x; v.y = (h1).y * (u1).y;                          \
        v.z = (h1).z * (u1).z; v.w = (h1).w * (u1).w; CVT4(v);                 \
        *(float4*)&A1[(fr + 32) * TSTR + fc] = v;                              \
        v = (d0); CVT4(v); *(float4*)&Bb[fr * TSTR + fc] = v;                  \
        v = (d1); CVT4(v); *(float4*)&Bb[(fr + 32) * TSTR + fc] = v;           \
        v = (d2); CVT4(v); *(float4*)&Bb[(fr + 64) * TSTR + fc] = v;           \
        v = (d3); CVT4(v); *(float4*)&Bb[(fr + 96) * TSTR + fc] = v;           \
    } while (0)

    // Fill stage 0 with chunk 0.
    {
        float4 h0 = *(const float4*)(hp);
        float4 h1 = *(const float4*)(hp + 32 * ND);
        float4 d0 = *(const float4*)(dp);
        float4 d1 = *(const float4*)(dp + 32 * ND);
        float4 d2 = *(const float4*)(dp + 64 * ND);
        float4 d3 = *(const float4*)(dp + 96 * ND);
        float4 u0 = *(const float4*)&Us[fc];
        float4 u1 = *(const float4*)&Us[ND + fc];
        FILL_STAGE(0, h0, h1, d0, d1, d2, d3, u0, u1);
    }
    __syncthreads();

    // Hoisted fragment-read bases (floats).
    const int arow = (wm * 32 + gid) * TSTR + tig;   // + mt*16*TSTR (+8*TSTR), +4
    const int brow = (wn * 32 + gid) * TSTR + tig;   // + nt*8*TSTR, +4

    for (int ch = 0; ch < NCH; ch++) {
        const int cur = ch & 1;
        const int k0 = ch * BK;
        const bool more = (ch < NCH - 1);

        // 1) LDG next chunk + next U slice (latency hidden under MMAs).
        float4 h0, h1, d0, d1, d2, d3, u0, u1;
        if (more) {
            h0 = *(const float4*)(hp + k0 + BK);
            h1 = *(const float4*)(hp + k0 + BK + 32 * ND);
            d0 = *(const float4*)(dp + k0 + BK);
            d1 = *(const float4*)(dp + k0 + BK + 32 * ND);
            d2 = *(const float4*)(dp + k0 + BK + 64 * ND);
            d3 = *(const float4*)(dp + k0 + BK + 96 * ND);
            u0 = *(const float4*)&Us[k0 + BK + fc];
            u1 = *(const float4*)&Us[ND + k0 + BK + fc];
        }

        // 2) MMAs on current stage: pure LDS + HMMA.
        const float* A0 = smf + cur * SF;
        const float* A1 = A0 + A_FLOATS;
        const float* Bc = A1 + A_FLOATS;
#pragma unroll
        for (int kt = 0; kt < 4; kt++) {
            const int kc = kt * 8;
            uint32_t a[LT][2][4];
#pragma unroll
            for (int mt = 0; mt < 2; mt++) {
                const int r = arow + mt * 16 * TSTR + kc;
                a[0][mt][0] = __float_as_uint(A0[r]);
                a[0][mt][1] = __float_as_uint(A0[r + 8 * TSTR]);
                a[0][mt][2] = __float_as_uint(A0[r + 4]);
                a[0][mt][3] = __float_as_uint(A0[r + 8 * TSTR + 4]);
                a[1][mt][0] = __float_as_uint(A1[r]);
                a[1][mt][1] = __float_as_uint(A1[r + 8 * TSTR]);
                a[1][mt][2] = __float_as_uint(A1[r + 4]);
                a[1][mt][3] = __float_as_uint(A1[r + 8 * TSTR + 4]);
            }
#pragma unroll
            for (int nt = 0; nt < 4; nt++) {
                const int cb = brow + nt * 8 * TSTR + kc;
                const uint32_t b0 = __float_as_uint(Bc[cb]);
                const uint32_t b1 = __float_as_uint(Bc[cb + 4]);
                mma_tf32(acc[0][0][nt], a[0][0], b0, b1);
                mma_tf32(acc[0][1][nt], a[0][1], b0, b1);
                mma_tf32(acc[1][0][nt], a[1][0], b0, b1);
                mma_tf32(acc[1][1][nt], a[1][1], b0, b1);
            }
        }

        // 3) scale + cvt + STS into the other stage.
        if (more) {
            FILL_STAGE(cur ^ 1, h0, h1, d0, d1, d2, d3, u0, u1);
            __syncthreads();   // one barrier per chunk
        }
    }

    // Epilogue: + rowadd[b,l,i] + coladd[b,l,o]  (bias folded into rowadd).
#pragma unroll
    for (int l = 0; l < LT; l++) {
        const int lg = l0 + l;
        const float* radd = &g_rowadd[((size_t)(b * NL + lg)) * NS + i0];
        const float* cadd = &g_coladd[((size_t)(b * NL + lg)) * NS + o0];
        float* op = out + (((size_t)(b * NL + lg)) * NS + i0) * NS + o0;
#pragma unroll
        for (int mt = 0; mt < 2; mt++) {
            const int r0 = wm * 32 + mt * 16 + gid;
            const float ra0 = radd[r0];
            const float ra1 = radd[r0 + 8];
#pragma unroll
            for (int nt = 0; nt < 4; nt++) {
                const int c = wn * 32 + nt * 8 + 2 * tig;
                const float2 ca = *(const float2*)&cadd[c];
                float2 v0, v1;
                v0.x = acc[l][mt][nt][0] + ra0 + ca.x;
                v0.y = acc[l][mt][nt][1] + ra0 + ca.y;
                v1.x = acc[l][mt][nt][2] + ra1 + ca.x;
                v1.y = acc[l][mt][nt][3] + ra1 + ca.y;
                *(float2*)&op[(size_t)r0 * NS + c]       = v0;
                *(float2*)&op[(size_t)(r0 + 8) * NS + c] = v1;
            }
        }
    }
}

extern "C" void kernel_launch(void* const* d_in, const int* in_sizes, int n_in,
                              void* d_out, int out_size) {
    const float* head = (const float*)d_in[0];
    const float* dep  = (const float*)d_in[1];
    const float* U    = (const float*)d_in[2];
    const float* W    = (const float*)d_in[3];
    const float* bias = (const float*)d_in[4];
    float* out = (float*)d_out;

    cudaFuncSetAttribute(biaffine_main_kernel,
                         cudaFuncAttributeMaxDynamicSharedMemorySize, SMEM_BYTES);

    stage1_kernel<<<dim3(NB * (NS / 32), 2), 256>>>(head, dep, W, bias);
    biaffine_main_kernel<<<dim3(NS / BN, NS / BM, NB * (NL / LT)), 256, SMEM_BYTES>>>(
        head, dep, U, out);
}